// round 3
// baseline (speedup 1.0000x reference)
#include <cuda_runtime.h>

// ============================================================================
// CAAN rank-gated attention, restructured:
//   q = S Wq^T + bq ; k = S Wk^T + bk                       (proj_kernel)
//   f[j] = S[j] . u + c,  u = Wv^T wf,  c = Wv_b . wf       (prep + f_kernel)
//   gate[d] = sigmoid(rank_emb[d] . wL + bL)                (prep_kernel)
//   x_ij = gate[floor(|r_i - r_j|/4)] * (q_i.k_j)/sqrt(128)
//   out_i = sigmoid( sum_j softmax_j(x_ij) * f_j + wf_b )   (attn + combine)
// ============================================================================

#define N_ASSETS 4096
#define D_MODEL  512
#define DK       128
#define NUM_EMB  1024
#define NCHUNK   4
#define KEYS_PER_CHUNK (N_ASSETS / NCHUNK)   // 1024
#define SCORE_SCALE 0.08838834764831845f     // 1/sqrt(128)

typedef unsigned long long ull;

// --------------------------- scratch (no allocs) ----------------------------
__device__ float d_Q[N_ASSETS * DK];
__device__ float d_K[N_ASSETS * DK];
__device__ float d_f[N_ASSETS];
__device__ float d_u[D_MODEL + 1];          // [512] = u, [512] = c
__device__ float d_gate[NUM_EMB];
__device__ float d_pm[NCHUNK * N_ASSETS];
__device__ float d_pl[NCHUNK * N_ASSETS];
__device__ float d_pw[NCHUNK * N_ASSETS];

// --------------------------- f32x2 helpers ----------------------------------
__device__ __forceinline__ ull pack2(float x, float y) {
    ull r; asm("mov.b64 %0, {%1, %2};" : "=l"(r) : "f"(x), "f"(y)); return r;
}
__device__ __forceinline__ float2 unpack2(ull v) {
    float2 f; asm("mov.b64 {%0, %1}, %2;" : "=f"(f.x), "=f"(f.y) : "l"(v)); return f;
}
__device__ __forceinline__ void fma2(ull& d, ull a, ull b) {
    asm("fma.rn.f32x2 %0, %1, %2, %0;" : "+l"(d) : "l"(a), "l"(b));
}

// ============================================================================
// prep: gate table (blocks 0-3), u vector (blocks 4-5), c scalar (block 6)
// ============================================================================
__global__ void prep_kernel(const float* __restrict__ rank_emb,
                            const float* __restrict__ wL_w,
                            const float* __restrict__ wL_b,
                            const float* __restrict__ Wv_w,
                            const float* __restrict__ Wv_b,
                            const float* __restrict__ wf_w) {
    int b = blockIdx.x, t = threadIdx.x;
    if (b < 4) {
        int d = b * 256 + t;
        float s = wL_b[0];
        #pragma unroll 8
        for (int e = 0; e < 32; e++) s += rank_emb[d * 32 + e] * wL_w[e];
        d_gate[d] = 1.0f / (1.0f + __expf(-s));
    } else if (b < 6) {
        int m = (b - 4) * 256 + t;
        float s = 0.f;
        for (int o = 0; o < D_MODEL; o++) s += Wv_w[o * D_MODEL + m] * wf_w[o];
        d_u[m] = s;
    } else {
        __shared__ float red[256];
        float s = 0.f;
        for (int o = t; o < D_MODEL; o += 256) s += wf_w[o] * Wv_b[o];
        red[t] = s; __syncthreads();
        for (int st = 128; st > 0; st >>= 1) {
            if (t < st) red[t] += red[t + st];
            __syncthreads();
        }
        if (t == 0) d_u[D_MODEL] = red[0];
    }
}

// ============================================================================
// proj: Q and K = S @ W^T + b. Grid (32, 4): y in {0,1}->Q cols {0-63,64-127},
// y in {2,3}->K. Tile 128(M) x 64(N), K chunks of 32, f32x2 over column pairs.
// ============================================================================
__global__ void __launch_bounds__(256) proj_kernel(
    const float* __restrict__ S,
    const float* __restrict__ Wq_w, const float* __restrict__ Wq_b,
    const float* __restrict__ Wk_w, const float* __restrict__ Wk_b) {
    __shared__ __align__(16) float sa[32][129];   // S chunk, kk-major
    __shared__ __align__(16) float sb[32][66];    // W chunk, kk-major (even pad for ld64)

    int tid = threadIdx.x;
    int tx = tid & 15, ty = tid >> 4;
    int rbase = blockIdx.x * 128;
    int by = blockIdx.y;
    const float* W    = (by < 2) ? Wq_w : Wk_w;
    const float* bias = (by < 2) ? Wq_b : Wk_b;
    float*       OUT  = (by < 2) ? d_Q  : d_K;
    int cofs = (by & 1) * 64;

    ull acc[8][2];
    #pragma unroll
    for (int i = 0; i < 8; i++) { acc[i][0] = 0ull; acc[i][1] = 0ull; }

    int lk = tid & 31;   // kk lane for loading
    int lr = tid >> 5;   // 0..7

    for (int kc = 0; kc < D_MODEL; kc += 32) {
        __syncthreads();
        #pragma unroll
        for (int t = 0; t < 16; t++) {
            int r = lr + 8 * t;
            sa[lk][r] = S[(rbase + r) * D_MODEL + kc + lk];
        }
        #pragma unroll
        for (int t = 0; t < 8; t++) {
            int c = lr + 8 * t;
            sb[lk][c] = W[(cofs + c) * D_MODEL + kc + lk];
        }
        __syncthreads();
        #pragma unroll
        for (int kk = 0; kk < 32; kk++) {
            ull bv0 = *(const ull*)&sb[kk][2 * tx];
            ull bv1 = *(const ull*)&sb[kk][2 * tx + 32];
            #pragma unroll
            for (int i = 0; i < 8; i++) {
                float a = sa[kk][ty + 16 * i];
                ull ap = pack2(a, a);
                fma2(acc[i][0], ap, bv0);
                fma2(acc[i][1], ap, bv1);
            }
        }
    }
    #pragma unroll
    for (int i = 0; i < 8; i++) {
        int row = rbase + ty + 16 * i;
        #pragma unroll
        for (int j = 0; j < 2; j++) {
            float2 v = unpack2(acc[i][j]);
            int c = 2 * tx + 32 * j;
            OUT[row * DK + cofs + c]     = v.x + bias[cofs + c];
            OUT[row * DK + cofs + c + 1] = v.y + bias[cofs + c + 1];
        }
    }
}

// ============================================================================
// f: f[i] = S[i] . u + c   (one warp per row)
// ============================================================================
__global__ void f_kernel(const float* __restrict__ S) {
    int warp = (blockIdx.x * blockDim.x + threadIdx.x) >> 5;
    int lane = threadIdx.x & 31;
    if (warp >= N_ASSETS) return;
    float s = 0.f;
    #pragma unroll
    for (int t = 0; t < 16; t++)
        s += S[warp * D_MODEL + lane + 32 * t] * d_u[lane + 32 * t];
    #pragma unroll
    for (int st = 16; st > 0; st >>= 1)
        s += __shfl_xor_sync(0xffffffffu, s, st);
    if (lane == 0) d_f[warp] = s + d_u[D_MODEL];
}

// ============================================================================
// attn: fused score + gate + online softmax + weighted-f accumulation.
// Grid (32 qblocks, 4 key chunks), 256 threads. Each CTA: 128 queries x 1024
// keys. 128x128 score tiles via f32x2 register GEMM; per-row (m,l,w) partials.
// Rows: r = ty + 16*i (i<8). Cols: c = 2*tx + 32*j + h (j<4, h<2).
// ============================================================================
__global__ void __launch_bounds__(256, 1) attn_kernel(const float* __restrict__ ranks) {
    __shared__ float gate_s[NUM_EMB];
    __shared__ __align__(16) float aq[32][129];   // Q chunk kk-major
    __shared__ __align__(16) float ak[32][130];   // K chunk kk-major (even pad for ld64)
    __shared__ float fk_s[128];
    __shared__ float rk_s[128];

    int tid = threadIdx.x;
    int tx = tid & 15, ty = tid >> 4;
    int qbase = blockIdx.x * 128;
    int cbase = blockIdx.y * KEYS_PER_CHUNK;

    #pragma unroll
    for (int t = 0; t < 4; t++) gate_s[tid + 256 * t] = d_gate[tid + 256 * t];

    float rq[8];
    #pragma unroll
    for (int i = 0; i < 8; i++) rq[i] = ranks[qbase + ty + 16 * i];

    float m_i[8], l_i[8], w_i[8];
    #pragma unroll
    for (int i = 0; i < 8; i++) { m_i[i] = -1e30f; l_i[i] = 0.f; w_i[i] = 0.f; }

    int lk = tid & 31, lr = tid >> 5;

    for (int kt = 0; kt < KEYS_PER_CHUNK / 128; kt++) {
        int kbase = cbase + kt * 128;
        ull acc[8][4];
        #pragma unroll
        for (int i = 0; i < 8; i++)
            #pragma unroll
            for (int j = 0; j < 4; j++) acc[i][j] = 0ull;

        for (int kc = 0; kc < DK; kc += 32) {
            __syncthreads();   // also separates previous epilogue reads from new writes
            #pragma unroll
            for (int t = 0; t < 16; t++) {
                int r = lr + 8 * t;
                aq[lk][r] = d_Q[(qbase + r) * DK + kc + lk];
                ak[lk][r] = d_K[(kbase + r) * DK + kc + lk];
            }
            if (kc == 0 && tid < 128) {
                fk_s[tid] = d_f[kbase + tid];
                rk_s[tid] = ranks[kbase + tid];
            }
            __syncthreads();
            #pragma unroll
            for (int kk = 0; kk < 32; kk++) {
                ull bv[4];
                #pragma unroll
                for (int j = 0; j < 4; j++)
                    bv[j] = *(const ull*)&ak[kk][2 * tx + 32 * j];
                #pragma unroll
                for (int i = 0; i < 8; i++) {
                    float a = aq[kk][ty + 16 * i];
                    ull ap = pack2(a, a);
                    #pragma unroll
                    for (int j = 0; j < 4; j++)
                        fma2(acc[i][j], ap, bv[j]);
                }
            }
        }

        // ---- epilogue: psi gate + online softmax over this 128-key tile ----
        float fc[8], rc[8];
        #pragma unroll
        for (int j = 0; j < 4; j++) {
            int c = 2 * tx + 32 * j;
            fc[2 * j] = fk_s[c];     fc[2 * j + 1] = fk_s[c + 1];
            rc[2 * j] = rk_s[c];     rc[2 * j + 1] = rk_s[c + 1];
        }
        #pragma unroll
        for (int i = 0; i < 8; i++) {
            float x[8];
            float tmax = -1e30f;
            #pragma unroll
            for (int j = 0; j < 4; j++) {
                float2 v = unpack2(acc[i][j]);
                float s0 = v.x * SCORE_SCALE;
                float s1 = v.y * SCORE_SCALE;
                int d0 = __float2int_rd(fabsf(rq[i] - rc[2 * j]) * 0.25f);
                int d1 = __float2int_rd(fabsf(rq[i] - rc[2 * j + 1]) * 0.25f);
                d0 = min(d0, NUM_EMB - 1);
                d1 = min(d1, NUM_EMB - 1);
                float x0 = gate_s[d0] * s0;
                float x1 = gate_s[d1] * s1;
                x[2 * j] = x0; x[2 * j + 1] = x1;
                tmax = fmaxf(tmax, fmaxf(x0, x1));
            }
            // row-wise reduce across the 16 tx lanes (stays within same ty half)
            #pragma unroll
            for (int st = 1; st < 16; st <<= 1)
                tmax = fmaxf(tmax, __shfl_xor_sync(0xffffffffu, tmax, st));
            float m_new = fmaxf(m_i[i], tmax);
            float tl = 0.f, tw = 0.f;
            #pragma unroll
            for (int e = 0; e < 8; e++) {
                float p = __expf(x[e] - m_new);
                tl += p; tw += p * fc[e];
            }
            #pragma unroll
            for (int st = 1; st < 16; st <<= 1) {
                tl += __shfl_xor_sync(0xffffffffu, tl, st);
                tw += __shfl_xor_sync(0xffffffffu, tw, st);
            }
            float scl = __expf(m_i[i] - m_new);
            l_i[i] = l_i[i] * scl + tl;
            w_i[i] = w_i[i] * scl + tw;
            m_i[i] = m_new;
        }
    }

    if (tx == 0) {   // all 16 tx lanes hold identical row state; one writer
        #pragma unroll
        for (int i = 0; i < 8; i++) {
            int row = qbase + ty + 16 * i;
            int idx = blockIdx.y * N_ASSETS + row;
            d_pm[idx] = m_i[i];
            d_pl[idx] = l_i[i];
            d_pw[idx] = w_i[i];
        }
    }
}

// ============================================================================
// combine: merge NCHUNK split-K softmax partials, final sigmoid
// ============================================================================
__global__ void combine_kernel(const float* __restrict__ wf_b, float* __restrict__ out) {
    int i = blockIdx.x * blockDim.x + threadIdx.x;
    if (i >= N_ASSETS) return;
    float M = -1e30f;
    #pragma unroll
    for (int c = 0; c < NCHUNK; c++) M = fmaxf(M, d_pm[c * N_ASSETS + i]);
    float L = 0.f, W = 0.f;
    #pragma unroll
    for (int c = 0; c < NCHUNK; c++) {
        float e = __expf(d_pm[c * N_ASSETS + i] - M);
        L += d_pl[c * N_ASSETS + i] * e;
        W += d_pw[c * N_ASSETS + i] * e;
    }
    float z = W / L + wf_b[0];
    out[i] = 1.0f / (1.0f + __expf(-z));
}

// ============================================================================
// launch
// ============================================================================
extern "C" void kernel_launch(void* const* d_in, const int* in_sizes, int n_in,
                              void* d_out, int out_size) {
    const float* S        = (const float*)d_in[0];
    const float* ranks    = (const float*)d_in[1];
    const float* Wq_w     = (const float*)d_in[2];
    const float* Wq_b     = (const float*)d_in[3];
    const float* Wk_w     = (const float*)d_in[4];
    const float* Wk_b     = (const float*)d_in[5];
    const float* Wv_w     = (const float*)d_in[6];
    const float* Wv_b     = (const float*)d_in[7];
    const float* rank_emb = (const float*)d_in[8];
    const float* wL_w     = (const float*)d_in[9];
    const float* wL_b     = (const float*)d_in[10];
    const float* wf_w     = (const float*)d_in[11];
    const float* wf_b     = (const float*)d_in[12];
    float* out = (float*)d_out;

    prep_kernel<<<7, 256>>>(rank_emb, wL_w, wL_b, Wv_w, Wv_b, wf_w);
    proj_kernel<<<dim3(32, 4), 256>>>(S, Wq_w, Wq_b, Wk_w, Wk_b);
    f_kernel<<<512, 256>>>(S);
    attn_kernel<<<dim3(32, NCHUNK), 256>>>(ranks);
    combine_kernel<<<16, 256>>>(wf_b, out);
}

// round 6
// speedup vs baseline: 1.8624x; 1.8624x over previous
#include <cuda_runtime.h>
#include <cuda_bf16.h>
#include <cstdint>

// ============================================================================
// CAAN rank-gated attention (sm_100 base target: mma.sync bf16 + cp.async):
//   q = S Wq^T + bq ; k = S Wk^T + bk      (proj -> bf16 hi/lo split)
//   f[j] = S[j].u + c, u = Wv^T wf         (prep + f)
//   gate'[d] = sigmoid(rank_emb[d].wL+bL)/sqrt(128)
//   x_ij = gate'[|ri-rj|/4] * (q_i.k_j)    (3-product bf16-split HMMA)
//   out_i = sigmoid( (sum_j e^x f_j)/(sum_j e^x) + wf_b )   (no-max softmax:
//   |x| <= ~2 so exp cannot overflow; ratios identical to softmax)
// ============================================================================

#define N_ASSETS 4096
#define D_MODEL  512
#define DK       128
#define NUM_EMB  1024
#define NCHUNK   4
#define KEYS_PER_CHUNK (N_ASSETS / NCHUNK)
#define SCORE_SCALE 0.08838834764831845f     // 1/sqrt(128)

typedef unsigned long long ull;

// --------------------------- scratch (no allocs) ----------------------------
__device__ __align__(16) __nv_bfloat16 d_Qh[N_ASSETS * DK];
__device__ __align__(16) __nv_bfloat16 d_Ql[N_ASSETS * DK];
__device__ __align__(16) __nv_bfloat16 d_Kh[N_ASSETS * DK];
__device__ __align__(16) __nv_bfloat16 d_Kl[N_ASSETS * DK];
__device__ float d_f[N_ASSETS];
__device__ float d_u[D_MODEL + 1];
__device__ float d_gate[NUM_EMB];            // premultiplied by SCORE_SCALE
__device__ float d_pl[NCHUNK * N_ASSETS];
__device__ float d_pw[NCHUNK * N_ASSETS];

// --------------------------- f32x2 helpers (proj) ---------------------------
__device__ __forceinline__ ull pack2(float x, float y) {
    ull r; asm("mov.b64 %0, {%1, %2};" : "=l"(r) : "f"(x), "f"(y)); return r;
}
__device__ __forceinline__ float2 unpack2(ull v) {
    float2 f; asm("mov.b64 {%0, %1}, %2;" : "=f"(f.x), "=f"(f.y) : "l"(v)); return f;
}
__device__ __forceinline__ void fma2(ull& d, ull a, ull b) {
    asm("fma.rn.f32x2 %0, %1, %2, %0;" : "+l"(d) : "l"(a), "l"(b));
}

// --------------------------- mma/ldsm/cp.async helpers -----------------------
__device__ __forceinline__ uint32_t smem_u32(const void* p) {
    uint32_t a;
    asm("{ .reg .u64 t; cvta.to.shared.u64 t, %1; cvt.u32.u64 %0, t; }"
        : "=r"(a) : "l"(p));
    return a;
}
__device__ __forceinline__ void ldsm4(uint32_t* r, uint32_t addr) {
    asm volatile("ldmatrix.sync.aligned.m8n8.x4.shared.b16 {%0,%1,%2,%3}, [%4];"
                 : "=r"(r[0]), "=r"(r[1]), "=r"(r[2]), "=r"(r[3]) : "r"(addr));
}
__device__ __forceinline__ void mma_bf16(float* c, const uint32_t* a, const uint32_t* b) {
    asm volatile(
        "mma.sync.aligned.m16n8k16.row.col.f32.bf16.bf16.f32 "
        "{%0,%1,%2,%3}, {%4,%5,%6,%7}, {%8,%9}, {%0,%1,%2,%3};"
        : "+f"(c[0]), "+f"(c[1]), "+f"(c[2]), "+f"(c[3])
        : "r"(a[0]), "r"(a[1]), "r"(a[2]), "r"(a[3]), "r"(b[0]), "r"(b[1]));
}
__device__ __forceinline__ void cp16(uint32_t dst, const void* src) {
    asm volatile("cp.async.cg.shared.global [%0], [%1], 16;" :: "r"(dst), "l"(src));
}
__device__ __forceinline__ void cp4(uint32_t dst, const void* src) {
    asm volatile("cp.async.ca.shared.global [%0], [%1], 4;" :: "r"(dst), "l"(src));
}
#define CP_COMMIT() asm volatile("cp.async.commit_group;" ::: "memory")
#define CP_WAIT0()  asm volatile("cp.async.wait_group 0;" ::: "memory")

// XOR swizzle of 16B-chunk index within a 256B row (16 chunks)
__device__ __forceinline__ int swz(int chunk, int row) {
    return (chunk & 8) | ((chunk ^ row) & 7);
}

// ============================================================================
// prep: gate table (blocks 0-3), u vector (blocks 4-5), c scalar (block 6)
// ============================================================================
__global__ void prep_kernel(const float* __restrict__ rank_emb,
                            const float* __restrict__ wL_w,
                            const float* __restrict__ wL_b,
                            const float* __restrict__ Wv_w,
                            const float* __restrict__ Wv_b,
                            const float* __restrict__ wf_w) {
    int b = blockIdx.x, t = threadIdx.x;
    if (b < 4) {
        int d = b * 256 + t;
        float s = wL_b[0];
        #pragma unroll 8
        for (int e = 0; e < 32; e++) s += rank_emb[d * 32 + e] * wL_w[e];
        d_gate[d] = SCORE_SCALE / (1.0f + __expf(-s));
    } else if (b < 6) {
        int m = (b - 4) * 256 + t;
        float s = 0.f;
        for (int o = 0; o < D_MODEL; o++) s += Wv_w[o * D_MODEL + m] * wf_w[o];
        d_u[m] = s;
    } else {
        __shared__ float red[256];
        float s = 0.f;
        for (int o = t; o < D_MODEL; o += 256) s += wf_w[o] * Wv_b[o];
        red[t] = s; __syncthreads();
        for (int st = 128; st > 0; st >>= 1) {
            if (t < st) red[t] += red[t + st];
            __syncthreads();
        }
        if (t == 0) d_u[D_MODEL] = red[0];
    }
}

// ============================================================================
// proj: Q,K = S @ W^T + b, written as bf16 hi/lo split pairs
// ============================================================================
__global__ void __launch_bounds__(256) proj_kernel(
    const float* __restrict__ S,
    const float* __restrict__ Wq_w, const float* __restrict__ Wq_b,
    const float* __restrict__ Wk_w, const float* __restrict__ Wk_b) {
    __shared__ __align__(16) float sa[32][129];
    __shared__ __align__(16) float sb[32][66];

    int tid = threadIdx.x;
    int tx = tid & 15, ty = tid >> 4;
    int rbase = blockIdx.x * 128;
    int by = blockIdx.y;
    const float* W    = (by < 2) ? Wq_w : Wk_w;
    const float* bias = (by < 2) ? Wq_b : Wk_b;
    __nv_bfloat16* OH = (by < 2) ? d_Qh : d_Kh;
    __nv_bfloat16* OL = (by < 2) ? d_Ql : d_Kl;
    int cofs = (by & 1) * 64;

    ull acc[8][2];
    #pragma unroll
    for (int i = 0; i < 8; i++) { acc[i][0] = 0ull; acc[i][1] = 0ull; }

    int lk = tid & 31, lr = tid >> 5;

    for (int kc = 0; kc < D_MODEL; kc += 32) {
        __syncthreads();
        #pragma unroll
        for (int t = 0; t < 16; t++) {
            int r = lr + 8 * t;
            sa[lk][r] = S[(rbase + r) * D_MODEL + kc + lk];
        }
        #pragma unroll
        for (int t = 0; t < 8; t++) {
            int c = lr + 8 * t;
            sb[lk][c] = W[(cofs + c) * D_MODEL + kc + lk];
        }
        __syncthreads();
        #pragma unroll
        for (int kk = 0; kk < 32; kk++) {
            ull bv0 = *(const ull*)&sb[kk][2 * tx];
            ull bv1 = *(const ull*)&sb[kk][2 * tx + 32];
            #pragma unroll
            for (int i = 0; i < 8; i++) {
                float a = sa[kk][ty + 16 * i];
                ull ap = pack2(a, a);
                fma2(acc[i][0], ap, bv0);
                fma2(acc[i][1], ap, bv1);
            }
        }
    }
    #pragma unroll
    for (int i = 0; i < 8; i++) {
        int row = rbase + ty + 16 * i;
        #pragma unroll
        for (int j = 0; j < 2; j++) {
            float2 v = unpack2(acc[i][j]);
            int c = 2 * tx + 32 * j;
            float v0 = v.x + bias[cofs + c];
            float v1 = v.y + bias[cofs + c + 1];
            __nv_bfloat16 h0 = __float2bfloat16(v0);
            __nv_bfloat16 h1 = __float2bfloat16(v1);
            OH[row * DK + cofs + c]     = h0;
            OH[row * DK + cofs + c + 1] = h1;
            OL[row * DK + cofs + c]     = __float2bfloat16(v0 - __bfloat162float(h0));
            OL[row * DK + cofs + c + 1] = __float2bfloat16(v1 - __bfloat162float(h1));
        }
    }
}

// ============================================================================
// f: f[i] = S[i] . u + c
// ============================================================================
__global__ void f_kernel(const float* __restrict__ S) {
    int warp = (blockIdx.x * blockDim.x + threadIdx.x) >> 5;
    int lane = threadIdx.x & 31;
    if (warp >= N_ASSETS) return;
    float s = 0.f;
    #pragma unroll
    for (int t = 0; t < 16; t++)
        s += S[warp * D_MODEL + lane + 32 * t] * d_u[lane + 32 * t];
    #pragma unroll
    for (int st = 16; st > 0; st >>= 1)
        s += __shfl_xor_sync(0xffffffffu, s, st);
    if (lane == 0) d_f[warp] = s + d_u[D_MODEL];
}

// ============================================================================
// attn: grid (32 qblocks, 4 chunks), 256 threads = 8 warps (2M x 4N).
// Per CTA: 128 q x 1024 k; 8 K-tiles of 128, double-buffered cp.async.
// Score via mma.sync bf16 3-product split; epilogue in registers.
// ============================================================================

// dynamic smem layout (bytes)
#define SM_GATE  0          // 4096
#define SM_RK    4096       // float[2][128]
#define SM_FK    5120       // float[2][128]
#define SM_PL    6144       // float[4][128]
#define SM_PW    8192       // float[4][128]
#define SM_QH    10240      // 32768
#define SM_QL    43008      // 32768
#define SM_KH    75776      // 2 x 32768
#define SM_KL    141312     // 2 x 32768
#define SMEM_TOTAL 206848

// async-copy one 128x128 bf16 tile (row-major, 256B/row) into swizzled smem
__device__ __forceinline__ void cp_tile(const __nv_bfloat16* __restrict__ g,
                                        uint32_t st_base) {
    int tid = threadIdx.x;
    #pragma unroll
    for (int i = 0; i < 8; i++) {
        int idx = tid + 256 * i;          // 0..2047 chunks
        int row = idx >> 4;
        int c   = idx & 15;
        uint32_t dst = st_base + row * 256 + swz(c, row) * 16;
        cp16(dst, (const char*)g + row * 256 + c * 16);
    }
}

__global__ void __launch_bounds__(256, 1) attn_kernel(const float* __restrict__ ranks) {
    extern __shared__ __align__(1024) char smem[];
    float* gate_s = (float*)(smem + SM_GATE);
    float* rk_s   = (float*)(smem + SM_RK);
    float* fk_s   = (float*)(smem + SM_FK);
    float* pl_s   = (float*)(smem + SM_PL);
    float* pw_s   = (float*)(smem + SM_PW);
    uint32_t sb = smem_u32(smem);

    int tid = threadIdx.x;
    int w = tid >> 5, lane = tid & 31;
    int wm = w >> 2, wn = w & 3;          // 2 x 4 warp grid
    int qbase = blockIdx.x * 128;
    int cbase = blockIdx.y * KEYS_PER_CHUNK;

    // gate table (premultiplied by SCORE_SCALE)
    #pragma unroll
    for (int t = 0; t < 4; t++) gate_s[tid + 256 * t] = d_gate[tid + 256 * t];

    // initial copies: Q hi/lo, K tile 0 hi/lo, rk/fk buf 0
    cp_tile(d_Qh + (size_t)qbase * DK, sb + SM_QH);
    cp_tile(d_Ql + (size_t)qbase * DK, sb + SM_QL);
    cp_tile(d_Kh + (size_t)cbase * DK, sb + SM_KH);
    cp_tile(d_Kl + (size_t)cbase * DK, sb + SM_KL);
    if (tid < 128) {
        cp4(sb + SM_RK + tid * 4, ranks + cbase + tid);
        cp4(sb + SM_FK + tid * 4, d_f + cbase + tid);
    }
    CP_COMMIT();

    // per-thread query rows: slot s = mi*2+h -> row = wm*64 + mi*16 + (lane>>2) + 8h
    float rq_t[8];
    #pragma unroll
    for (int s = 0; s < 8; s++)
        rq_t[s] = ranks[qbase + wm * 64 + (s >> 1) * 16 + (lane >> 2) + 8 * (s & 1)];

    float l_t[8], w_t[8];
    #pragma unroll
    for (int s = 0; s < 8; s++) { l_t[s] = 0.f; w_t[s] = 0.f; }

    float acc[4][4][4];
    #pragma unroll
    for (int mi = 0; mi < 4; mi++)
        #pragma unroll
        for (int nf = 0; nf < 4; nf++)
            #pragma unroll
            for (int e = 0; e < 4; e++) acc[mi][nf][e] = 0.f;

    CP_WAIT0();
    __syncthreads();

    // ldmatrix lane-address components
    int a_row  = (lane & 15);             // + wm*64 + mi*16
    int a_hi   = lane >> 4;               // k-chunk offset
    int b_nloc = (lane & 7) | ((lane >> 1) & 8);
    int b_hi   = (lane >> 3) & 1;

    for (int kt = 0; kt < 8; kt++) {
        int buf = kt & 1;
        uint32_t KHb = sb + SM_KH + buf * 32768;
        uint32_t KLb = sb + SM_KL + buf * 32768;

        // prefetch next tile
        if (kt < 7) {
            int kb = cbase + (kt + 1) * 128;
            int nb = buf ^ 1;
            cp_tile(d_Kh + (size_t)kb * DK, sb + SM_KH + nb * 32768);
            cp_tile(d_Kl + (size_t)kb * DK, sb + SM_KL + nb * 32768);
            if (tid < 128) {
                cp4(sb + SM_RK + (nb * 128 + tid) * 4, ranks + kb + tid);
                cp4(sb + SM_FK + (nb * 128 + tid) * 4, d_f + kb + tid);
            }
        }
        CP_COMMIT();

        // ---- 384 mma over k = 128 (8 k-steps, 3 products) ----
        #pragma unroll
        for (int ks = 0; ks < 8; ks++) {
            uint32_t Bh[2][4], Bl[2][4];
            int cB = 2 * ks + b_hi;
            #pragma unroll
            for (int np = 0; np < 2; np++) {
                int nrow = wn * 32 + np * 16 + b_nloc;
                uint32_t off = nrow * 256 + swz(cB, nrow) * 16;
                ldsm4(Bh[np], KHb + off);
                ldsm4(Bl[np], KLb + off);
            }
            #pragma unroll
            for (int mi = 0; mi < 4; mi++) {
                uint32_t Ah[4], Al[4];
                int qrow = wm * 64 + mi * 16 + a_row;
                int cA = 2 * ks + a_hi;
                uint32_t off = qrow * 256 + swz(cA, qrow) * 16;
                ldsm4(Ah, sb + SM_QH + off);
                ldsm4(Al, sb + SM_QL + off);
                #pragma unroll
                for (int nf = 0; nf < 4; nf++) {
                    float* c = acc[mi][nf];
                    const uint32_t* bh = &Bh[nf >> 1][(nf & 1) * 2];
                    const uint32_t* bl = &Bl[nf >> 1][(nf & 1) * 2];
                    mma_bf16(c, Ah, bh);
                    mma_bf16(c, Ah, bl);
                    mma_bf16(c, Al, bh);
                }
            }
        }

        // ---- epilogue in registers: gate + exp + l/w accumulation ----
        float rk_t[8], fk_t[8];
        #pragma unroll
        for (int nf = 0; nf < 4; nf++)
            #pragma unroll
            for (int h = 0; h < 2; h++) {
                int c = buf * 128 + wn * 32 + nf * 8 + 2 * (lane & 3) + h;
                rk_t[nf * 2 + h] = rk_s[c];
                fk_t[nf * 2 + h] = fk_s[c];
            }
        #pragma unroll
        for (int mi = 0; mi < 4; mi++)
            #pragma unroll
            for (int nf = 0; nf < 4; nf++)
                #pragma unroll
                for (int e = 0; e < 4; e++) {
                    int s = mi * 2 + (e >> 1);
                    int ci = nf * 2 + (e & 1);
                    int di = __float2int_rd(fabsf(rq_t[s] - rk_t[ci]) * 0.25f);
                    di = min(di, NUM_EMB - 1);
                    float x = gate_s[di] * acc[mi][nf][e];
                    float p = __expf(x);
                    l_t[s] += p;
                    w_t[s] += p * fk_t[ci];
                    acc[mi][nf][e] = 0.f;
                }

        CP_WAIT0();
        __syncthreads();
    }

    // ---- reduce: quad (cols within warp), then across 4 N-warps via smem ----
    #pragma unroll
    for (int s = 0; s < 8; s++) {
        #pragma unroll
        for (int st = 1; st < 4; st <<= 1) {
            l_t[s] += __shfl_xor_sync(0xffffffffu, l_t[s], st);
            w_t[s] += __shfl_xor_sync(0xffffffffu, w_t[s], st);
        }
    }
    if ((lane & 3) == 0) {
        #pragma unroll
        for (int s = 0; s < 8; s++) {
            int row = wm * 64 + (s >> 1) * 16 + (lane >> 2) + 8 * (s & 1);
            pl_s[wn * 128 + row] = l_t[s];
            pw_s[wn * 128 + row] = w_t[s];
        }
    }
    __syncthreads();
    if (tid < 128) {
        float L = 0.f, W = 0.f;
        #pragma unroll
        for (int k = 0; k < 4; k++) {
            L += pl_s[k * 128 + tid];
            W += pw_s[k * 128 + tid];
        }
        int idx = blockIdx.y * N_ASSETS + qbase + tid;
        d_pl[idx] = L;
        d_pw[idx] = W;
    }
}

// ============================================================================
// combine: merge NCHUNK partial sums, final sigmoid
// ============================================================================
__global__ void combine_kernel(const float* __restrict__ wf_b, float* __restrict__ out) {
    int i = blockIdx.x * blockDim.x + threadIdx.x;
    if (i >= N_ASSETS) return;
    float L = 0.f, W = 0.f;
    #pragma unroll
    for (int c = 0; c < NCHUNK; c++) {
        L += d_pl[c * N_ASSETS + i];
        W += d_pw[c * N_ASSETS + i];
    }
    float z = W / L + wf_b[0];
    out[i] = 1.0f / (1.0f + __expf(-z));
}

// ============================================================================
// launch
// ============================================================================
extern "C" void kernel_launch(void* const* d_in, const int* in_sizes, int n_in,
                              void* d_out, int out_size) {
    const float* S        = (const float*)d_in[0];
    const float* ranks    = (const float*)d_in[1];
    const float* Wq_w     = (const float*)d_in[2];
    const float* Wq_b     = (const float*)d_in[3];
    const float* Wk_w     = (const float*)d_in[4];
    const float* Wk_b     = (const float*)d_in[5];
    const float* Wv_w     = (const float*)d_in[6];
    const float* Wv_b     = (const float*)d_in[7];
    const float* rank_emb = (const float*)d_in[8];
    const float* wL_w     = (const float*)d_in[9];
    const float* wL_b     = (const float*)d_in[10];
    const float* wf_w     = (const float*)d_in[11];
    const float* wf_b     = (const float*)d_in[12];
    float* out = (float*)d_out;

    static int attr_set = 0;
    if (!attr_set) {
        cudaFuncSetAttribute(attn_kernel,
                             cudaFuncAttributeMaxDynamicSharedMemorySize, SMEM_TOTAL);
        attr_set = 1;
    }

    prep_kernel<<<7, 256>>>(rank_emb, wL_w, wL_b, Wv_w, Wv_b, wf_w);
    proj_kernel<<<dim3(32, 4), 256>>>(S, Wq_w, Wq_b, Wk_w, Wk_b);
    f_kernel<<<512, 256>>>(S);
    attn_kernel<<<dim3(32, NCHUNK), 256, SMEM_TOTAL>>>(ranks);
    combine_kernel<<<16, 256>>>(wf_b, out);
}

// round 7
// speedup vs baseline: 2.7126x; 1.4565x over previous
#include <cuda_runtime.h>
#include <cuda_bf16.h>
#include <cstdint>

// ============================================================================
// CAAN rank-gated attention (sm_100 base: mma.sync bf16 + cp.async):
//   Sh/Sl = bf16 split of S; f[i] = S[i].u + c (fused into convS)
//   Q,K   = S Wq^T/Wk^T via 3-product bf16-split HMMA, re-split to bf16 hi/lo
//   gate'[d] = sigmoid(rank_emb[d].wL+bL)/sqrt(128)
//   x_ij = gate'[|ri-rj|/4] * (q_i.k_j)   (3-product bf16-split HMMA)
//   out_i = sigmoid( (sum_j e^x f_j)/(sum_j e^x) + wf_b )  (no-max softmax:
//   |x| <= ~2 so exp cannot overflow; ratios identical to softmax)
// ============================================================================

#define N_ASSETS 4096
#define D_MODEL  512
#define DK       128
#define NUM_EMB  1024
#define NCHUNK   4
#define KEYS_PER_CHUNK (N_ASSETS / NCHUNK)
#define SCORE_SCALE 0.08838834764831845f     // 1/sqrt(128)

typedef unsigned long long ull;

// --------------------------- scratch (no allocs) ----------------------------
__device__ __align__(16) __nv_bfloat16 d_Sh[N_ASSETS * D_MODEL];
__device__ __align__(16) __nv_bfloat16 d_Sl[N_ASSETS * D_MODEL];
__device__ __align__(16) __nv_bfloat16 d_Wh[256 * D_MODEL];   // rows 0-127 Wq, 128-255 Wk
__device__ __align__(16) __nv_bfloat16 d_Wl[256 * D_MODEL];
__device__ __align__(16) __nv_bfloat16 d_Qh[N_ASSETS * DK];
__device__ __align__(16) __nv_bfloat16 d_Ql[N_ASSETS * DK];
__device__ __align__(16) __nv_bfloat16 d_Kh[N_ASSETS * DK];
__device__ __align__(16) __nv_bfloat16 d_Kl[N_ASSETS * DK];
__device__ float d_f[N_ASSETS];
__device__ float d_u[D_MODEL + 1];
__device__ float d_gate[NUM_EMB];            // premultiplied by SCORE_SCALE
__device__ float d_pl[NCHUNK * N_ASSETS];
__device__ float d_pw[NCHUNK * N_ASSETS];

// --------------------------- mma/ldsm/cp.async helpers -----------------------
__device__ __forceinline__ uint32_t smem_u32(const void* p) {
    uint32_t a;
    asm("{ .reg .u64 t; cvta.to.shared.u64 t, %1; cvt.u32.u64 %0, t; }"
        : "=r"(a) : "l"(p));
    return a;
}
__device__ __forceinline__ void ldsm4(uint32_t* r, uint32_t addr) {
    asm volatile("ldmatrix.sync.aligned.m8n8.x4.shared.b16 {%0,%1,%2,%3}, [%4];"
                 : "=r"(r[0]), "=r"(r[1]), "=r"(r[2]), "=r"(r[3]) : "r"(addr));
}
__device__ __forceinline__ void mma_bf16(float* c, const uint32_t* a, const uint32_t* b) {
    asm volatile(
        "mma.sync.aligned.m16n8k16.row.col.f32.bf16.bf16.f32 "
        "{%0,%1,%2,%3}, {%4,%5,%6,%7}, {%8,%9}, {%0,%1,%2,%3};"
        : "+f"(c[0]), "+f"(c[1]), "+f"(c[2]), "+f"(c[3])
        : "r"(a[0]), "r"(a[1]), "r"(a[2]), "r"(a[3]), "r"(b[0]), "r"(b[1]));
}
__device__ __forceinline__ void cp16(uint32_t dst, const void* src) {
    asm volatile("cp.async.cg.shared.global [%0], [%1], 16;" :: "r"(dst), "l"(src));
}
__device__ __forceinline__ void cp4(uint32_t dst, const void* src) {
    asm volatile("cp.async.ca.shared.global [%0], [%1], 4;" :: "r"(dst), "l"(src));
}
#define CP_COMMIT() asm volatile("cp.async.commit_group;" ::: "memory")
#define CP_WAIT0()  asm volatile("cp.async.wait_group 0;" ::: "memory")

// XOR swizzle of 16B-chunk index within a 256B row (16 chunks)
__device__ __forceinline__ int swz(int chunk, int row) {
    return (chunk & 8) | ((chunk ^ row) & 7);
}
__device__ __forceinline__ void bf16_split(float v, __nv_bfloat16& h, __nv_bfloat16& l) {
    h = __float2bfloat16(v);
    l = __float2bfloat16(v - __bfloat162float(h));
}

// ============================================================================
// prep: gate (b 0-3), u (b 4-19), c (b 20), W bf16 split (b 21-84)
// ============================================================================
__global__ void prep_kernel(const float* __restrict__ rank_emb,
                            const float* __restrict__ wL_w,
                            const float* __restrict__ wL_b,
                            const float* __restrict__ Wv_w,
                            const float* __restrict__ wf_w,
                            const float* __restrict__ Wv_b,
                            const float* __restrict__ Wq_w,
                            const float* __restrict__ Wk_w) {
    int b = blockIdx.x, t = threadIdx.x;
    if (b < 4) {
        int d = b * 256 + t;
        float s = wL_b[0];
        #pragma unroll 8
        for (int e = 0; e < 32; e++) s += rank_emb[d * 32 + e] * wL_w[e];
        d_gate[d] = SCORE_SCALE / (1.0f + __expf(-s));
    } else if (b < 20) {
        // u[m] = sum_o Wv_w[o*512+m] * wf[o]; 32 m per block, 8-way o split
        int b2 = b - 4;
        int mloc = t & 31, oo = t >> 5;
        int m = b2 * 32 + mloc;
        float s = 0.f;
        #pragma unroll 4
        for (int o = oo; o < D_MODEL; o += 8) s += Wv_w[o * D_MODEL + m] * wf_w[o];
        __shared__ float red[256];
        red[t] = s; __syncthreads();
        if (t < 32) {
            float x = red[t];
            #pragma unroll
            for (int i = 1; i < 8; i++) x += red[t + 32 * i];
            d_u[m] = x;
        }
    } else if (b == 20) {
        __shared__ float red[256];
        float s = 0.f;
        for (int o = t; o < D_MODEL; o += 256) s += wf_w[o] * Wv_b[o];
        red[t] = s; __syncthreads();
        for (int st = 128; st > 0; st >>= 1) {
            if (t < st) red[t] += red[t + st];
            __syncthreads();
        }
        if (t == 0) d_u[D_MODEL] = red[0];
    } else {
        // W split: 64 blocks x 256 thr x 8 elems = 131072 = 256*512
        int g0 = (b - 21) * 2048 + t * 8;
        #pragma unroll
        for (int j = 0; j < 2; j++) {
            float4 v = (g0 + 4 * j < 65536)
                ? *(const float4*)(Wq_w + g0 + 4 * j)
                : *(const float4*)(Wk_w + g0 + 4 * j - 65536);
            float vv[4] = {v.x, v.y, v.z, v.w};
            #pragma unroll
            for (int e = 0; e < 4; e++) {
                __nv_bfloat16 h, l;
                bf16_split(vv[e], h, l);
                d_Wh[g0 + 4 * j + e] = h;
                d_Wl[g0 + 4 * j + e] = l;
            }
        }
    }
}

// ============================================================================
// convS: split S into bf16 hi/lo AND compute f[i] = S[i].u + c (one pass)
// grid 128 x 256 thr; block handles 32 rows (warp -> 4 rows)
// ============================================================================
__global__ void __launch_bounds__(256) convS_kernel(const float* __restrict__ S) {
    __shared__ float u_s[D_MODEL];
    int tid = threadIdx.x, w = tid >> 5, lane = tid & 31;
    #pragma unroll
    for (int t = 0; t < 2; t++) u_s[tid + 256 * t] = d_u[tid + 256 * t];
    __syncthreads();
    float c = d_u[D_MODEL];

    int rbase = blockIdx.x * 32 + w * 4;
    #pragma unroll
    for (int rr = 0; rr < 4; rr++) {
        int row = rbase + rr;
        const float2* src = (const float2*)(S + (size_t)row * D_MODEL);
        __nv_bfloat162* dh = (__nv_bfloat162*)(d_Sh + (size_t)row * D_MODEL);
        __nv_bfloat162* dl = (__nv_bfloat162*)(d_Sl + (size_t)row * D_MODEL);
        float s = 0.f;
        #pragma unroll
        for (int t = 0; t < 8; t++) {
            int e2 = lane + 32 * t;
            float2 v = src[e2];
            s += v.x * u_s[2 * e2] + v.y * u_s[2 * e2 + 1];
            __nv_bfloat16 h0, l0, h1, l1;
            bf16_split(v.x, h0, l0);
            bf16_split(v.y, h1, l1);
            dh[e2] = __nv_bfloat162(h0, h1);
            dl[e2] = __nv_bfloat162(l0, l1);
        }
        #pragma unroll
        for (int st = 16; st > 0; st >>= 1)
            s += __shfl_xor_sync(0xffffffffu, s, st);
        if (lane == 0) d_f[row] = s + c;
    }
}

// ============================================================================
// proj_mma: Q/K = S @ W^T + b via 3-product bf16 HMMA, outputs bf16 hi/lo.
// grid (64 M-tiles of 64 rows, 2 = {Q,K}), 256 thr = 8 warps (2M x 4N).
// ============================================================================
#define PSM_BIAS 0          // 512B
#define PSM_SH   1024       // 64*256 = 16384
#define PSM_SL   17408
#define PSM_WH   33792      // 128*256 = 32768
#define PSM_WL   66560
#define PSM_TOTAL 99328

__global__ void __launch_bounds__(256, 1) proj_mma_kernel(
    const float* __restrict__ Wq_b, const float* __restrict__ Wk_b) {
    extern __shared__ __align__(1024) char smem[];
    uint32_t sb = smem_u32(smem);
    float* bias_s = (float*)(smem + PSM_BIAS);

    int tid = threadIdx.x;
    int w = tid >> 5, lane = tid & 31;
    int wm = w >> 2, wn = w & 3;
    int mbase = blockIdx.x * 64;
    int by = blockIdx.y;                 // 0 = Q, 1 = K

    if (tid < 128) bias_s[tid] = (by ? Wk_b : Wq_b)[tid];

    float acc[2][4][4];
    #pragma unroll
    for (int mi = 0; mi < 2; mi++)
        #pragma unroll
        for (int nf = 0; nf < 4; nf++)
            #pragma unroll
            for (int e = 0; e < 4; e++) acc[mi][nf][e] = 0.f;

    int a_row  = lane & 15, a_hi = lane >> 4;
    int b_nloc = (lane & 7) | ((lane >> 1) & 8);
    int b_hi   = (lane >> 3) & 1;

    for (int kc = 0; kc < 4; kc++) {
        __syncthreads();
        // S chunk: 64 rows x 128 cols (hi+lo): 1024 chunks each
        #pragma unroll
        for (int i = 0; i < 4; i++) {
            int idx = tid + 256 * i;
            int row = idx >> 4, c = idx & 15;
            const __nv_bfloat16* gs = d_Sh + (size_t)(mbase + row) * D_MODEL + kc * 128 + c * 8;
            cp16(sb + PSM_SH + row * 256 + swz(c, row) * 16, gs);
            const __nv_bfloat16* gl = d_Sl + (size_t)(mbase + row) * D_MODEL + kc * 128 + c * 8;
            cp16(sb + PSM_SL + row * 256 + swz(c, row) * 16, gl);
        }
        // W chunk: 128 rows x 128 cols (hi+lo): 2048 chunks each
        #pragma unroll
        for (int i = 0; i < 8; i++) {
            int idx = tid + 256 * i;
            int row = idx >> 4, c = idx & 15;
            const __nv_bfloat16* gh = d_Wh + (size_t)(by * 128 + row) * D_MODEL + kc * 128 + c * 8;
            cp16(sb + PSM_WH + row * 256 + swz(c, row) * 16, gh);
            const __nv_bfloat16* gl = d_Wl + (size_t)(by * 128 + row) * D_MODEL + kc * 128 + c * 8;
            cp16(sb + PSM_WL + row * 256 + swz(c, row) * 16, gl);
        }
        CP_COMMIT();
        CP_WAIT0();
        __syncthreads();

        #pragma unroll
        for (int ks = 0; ks < 8; ks++) {
            uint32_t Bh[2][4], Bl[2][4];
            int cB = 2 * ks + b_hi;
            #pragma unroll
            for (int np = 0; np < 2; np++) {
                int nrow = wn * 32 + np * 16 + b_nloc;
                uint32_t off = nrow * 256 + swz(cB, nrow) * 16;
                ldsm4(Bh[np], sb + PSM_WH + off);
                ldsm4(Bl[np], sb + PSM_WL + off);
            }
            #pragma unroll
            for (int mi = 0; mi < 2; mi++) {
                uint32_t Ah[4], Al[4];
                int qrow = wm * 32 + mi * 16 + a_row;
                int cA = 2 * ks + a_hi;
                uint32_t off = qrow * 256 + swz(cA, qrow) * 16;
                ldsm4(Ah, sb + PSM_SH + off);
                ldsm4(Al, sb + PSM_SL + off);
                #pragma unroll
                for (int nf = 0; nf < 4; nf++) {
                    float* cc = acc[mi][nf];
                    const uint32_t* bh = &Bh[nf >> 1][(nf & 1) * 2];
                    const uint32_t* bl = &Bl[nf >> 1][(nf & 1) * 2];
                    mma_bf16(cc, Ah, bh);
                    mma_bf16(cc, Ah, bl);
                    mma_bf16(cc, Al, bh);
                }
            }
        }
    }

    // epilogue: + bias, split to bf16 hi/lo, store pairs
    __nv_bfloat16* OH = by ? d_Kh : d_Qh;
    __nv_bfloat16* OL = by ? d_Kl : d_Ql;
    #pragma unroll
    for (int mi = 0; mi < 2; mi++)
        #pragma unroll
        for (int nf = 0; nf < 4; nf++)
            #pragma unroll
            for (int hrow = 0; hrow < 2; hrow++) {
                int row = mbase + wm * 32 + mi * 16 + (lane >> 2) + 8 * hrow;
                int col = wn * 32 + nf * 8 + 2 * (lane & 3);
                float v0 = acc[mi][nf][2 * hrow]     + bias_s[col];
                float v1 = acc[mi][nf][2 * hrow + 1] + bias_s[col + 1];
                __nv_bfloat16 h0, l0, h1, l1;
                bf16_split(v0, h0, l0);
                bf16_split(v1, h1, l1);
                *(__nv_bfloat162*)(OH + (size_t)row * DK + col) = __nv_bfloat162(h0, h1);
                *(__nv_bfloat162*)(OL + (size_t)row * DK + col) = __nv_bfloat162(l0, l1);
            }
}

// ============================================================================
// attn: grid (32 qblocks, 4 chunks), 512 threads = 16 warps (4M x 4N).
// Warp tile 32x32. 8 K-tiles of 128, double-buffered cp.async.
// ============================================================================
#define SM_GATE  0          // 4096
#define SM_RK    4096       // float[2][128]
#define SM_FK    5120
#define SM_PL    6144       // float[4][128]
#define SM_PW    8192
#define SM_QH    10240      // 32768
#define SM_QL    43008
#define SM_KH    75776      // 2 x 32768
#define SM_KL    141312
#define SMEM_TOTAL 206848

__device__ __forceinline__ void cp_tile(const __nv_bfloat16* __restrict__ g,
                                        uint32_t st_base) {
    int tid = threadIdx.x;
    #pragma unroll
    for (int i = 0; i < 4; i++) {
        int idx = tid + 512 * i;
        int row = idx >> 4, c = idx & 15;
        cp16(st_base + row * 256 + swz(c, row) * 16, (const char*)g + row * 256 + c * 16);
    }
}

__global__ void __launch_bounds__(512, 1) attn_kernel(const float* __restrict__ ranks) {
    extern __shared__ __align__(1024) char smem[];
    float* gate_s = (float*)(smem + SM_GATE);
    float* rk_s   = (float*)(smem + SM_RK);
    float* fk_s   = (float*)(smem + SM_FK);
    float* pl_s   = (float*)(smem + SM_PL);
    float* pw_s   = (float*)(smem + SM_PW);
    uint32_t sb = smem_u32(smem);

    int tid = threadIdx.x;
    int w = tid >> 5, lane = tid & 31;
    int wm = w >> 2, wn = w & 3;          // 4 x 4 warp grid
    int qbase = blockIdx.x * 128;
    int cbase = blockIdx.y * KEYS_PER_CHUNK;

    #pragma unroll
    for (int t = 0; t < 2; t++) gate_s[tid + 512 * t] = d_gate[tid + 512 * t];

    cp_tile(d_Qh + (size_t)qbase * DK, sb + SM_QH);
    cp_tile(d_Ql + (size_t)qbase * DK, sb + SM_QL);
    cp_tile(d_Kh + (size_t)cbase * DK, sb + SM_KH);
    cp_tile(d_Kl + (size_t)cbase * DK, sb + SM_KL);
    if (tid < 128) {
        cp4(sb + SM_RK + tid * 4, ranks + cbase + tid);
        cp4(sb + SM_FK + tid * 4, d_f + cbase + tid);
    }
    CP_COMMIT();

    // per-thread rows: slot s = mi*2+h -> row = wm*32 + mi*16 + (lane>>2) + 8h
    float rq_t[4];
    #pragma unroll
    for (int s = 0; s < 4; s++)
        rq_t[s] = ranks[qbase + wm * 32 + (s >> 1) * 16 + (lane >> 2) + 8 * (s & 1)];

    float l_t[4], w_t[4];
    #pragma unroll
    for (int s = 0; s < 4; s++) { l_t[s] = 0.f; w_t[s] = 0.f; }

    float acc[2][4][4];
    #pragma unroll
    for (int mi = 0; mi < 2; mi++)
        #pragma unroll
        for (int nf = 0; nf < 4; nf++)
            #pragma unroll
            for (int e = 0; e < 4; e++) acc[mi][nf][e] = 0.f;

    CP_WAIT0();
    __syncthreads();

    int a_row  = lane & 15, a_hi = lane >> 4;
    int b_nloc = (lane & 7) | ((lane >> 1) & 8);
    int b_hi   = (lane >> 3) & 1;

    for (int kt = 0; kt < 8; kt++) {
        int buf = kt & 1;
        uint32_t KHb = sb + SM_KH + buf * 32768;
        uint32_t KLb = sb + SM_KL + buf * 32768;

        if (kt < 7) {
            int kb = cbase + (kt + 1) * 128;
            int nb = buf ^ 1;
            cp_tile(d_Kh + (size_t)kb * DK, sb + SM_KH + nb * 32768);
            cp_tile(d_Kl + (size_t)kb * DK, sb + SM_KL + nb * 32768);
            if (tid < 128) {
                cp4(sb + SM_RK + (nb * 128 + tid) * 4, ranks + kb + tid);
                cp4(sb + SM_FK + (nb * 128 + tid) * 4, d_f + kb + tid);
            }
        }
        CP_COMMIT();

        #pragma unroll
        for (int ks = 0; ks < 8; ks++) {
            uint32_t Bh[2][4], Bl[2][4];
            int cB = 2 * ks + b_hi;
            #pragma unroll
            for (int np = 0; np < 2; np++) {
                int nrow = wn * 32 + np * 16 + b_nloc;
                uint32_t off = nrow * 256 + swz(cB, nrow) * 16;
                ldsm4(Bh[np], KHb + off);
                ldsm4(Bl[np], KLb + off);
            }
            #pragma unroll
            for (int mi = 0; mi < 2; mi++) {
                uint32_t Ah[4], Al[4];
                int qrow = wm * 32 + mi * 16 + a_row;
                int cA = 2 * ks + a_hi;
                uint32_t off = qrow * 256 + swz(cA, qrow) * 16;
                ldsm4(Ah, sb + SM_QH + off);
                ldsm4(Al, sb + SM_QL + off);
                #pragma unroll
                for (int nf = 0; nf < 4; nf++) {
                    float* c = acc[mi][nf];
                    const uint32_t* bh = &Bh[nf >> 1][(nf & 1) * 2];
                    const uint32_t* bl = &Bl[nf >> 1][(nf & 1) * 2];
                    mma_bf16(c, Ah, bh);
                    mma_bf16(c, Ah, bl);
                    mma_bf16(c, Al, bh);
                }
            }
        }

        // epilogue in registers
        float rk_t[8], fk_t[8];
        #pragma unroll
        for (int nf = 0; nf < 4; nf++)
            #pragma unroll
            for (int h = 0; h < 2; h++) {
                int c = buf * 128 + wn * 32 + nf * 8 + 2 * (lane & 3) + h;
                rk_t[nf * 2 + h] = rk_s[c];
                fk_t[nf * 2 + h] = fk_s[c];
            }
        #pragma unroll
        for (int mi = 0; mi < 2; mi++)
            #pragma unroll
            for (int nf = 0; nf < 4; nf++)
                #pragma unroll
                for (int e = 0; e < 4; e++) {
                    int s = mi * 2 + (e >> 1);
                    int ci = nf * 2 + (e & 1);
                    int di = __float2int_rd(fabsf(rq_t[s] - rk_t[ci]) * 0.25f);
                    di = min(di, NUM_EMB - 1);
                    float x = gate_s[di] * acc[mi][nf][e];
                    float p = __expf(x);
                    l_t[s] += p;
                    w_t[s] += p * fk_t[ci];
                    acc[mi][nf][e] = 0.f;
                }

        CP_WAIT0();
        __syncthreads();
    }

    // quad reduce (cols within warp), then across 4 N-warps via smem
    #pragma unroll
    for (int s = 0; s < 4; s++) {
        #pragma unroll
        for (int st = 1; st < 4; st <<= 1) {
            l_t[s] += __shfl_xor_sync(0xffffffffu, l_t[s], st);
            w_t[s] += __shfl_xor_sync(0xffffffffu, w_t[s], st);
        }
    }
    if ((lane & 3) == 0) {
        #pragma unroll
        for (int s = 0; s < 4; s++) {
            int row = wm * 32 + (s >> 1) * 16 + (lane >> 2) + 8 * (s & 1);
            pl_s[wn * 128 + row] = l_t[s];
            pw_s[wn * 128 + row] = w_t[s];
        }
    }
    __syncthreads();
    if (tid < 128) {
        float L = 0.f, W = 0.f;
        #pragma unroll
        for (int k = 0; k < 4; k++) {
            L += pl_s[k * 128 + tid];
            W += pw_s[k * 128 + tid];
        }
        int idx = blockIdx.y * N_ASSETS + qbase + tid;
        d_pl[idx] = L;
        d_pw[idx] = W;
    }
}

// ============================================================================
// combine: merge NCHUNK partial sums, final sigmoid
// ============================================================================
__global__ void combine_kernel(const float* __restrict__ wf_b, float* __restrict__ out) {
    int i = blockIdx.x * blockDim.x + threadIdx.x;
    if (i >= N_ASSETS) return;
    float L = 0.f, W = 0.f;
    #pragma unroll
    for (int c = 0; c < NCHUNK; c++) {
        L += d_pl[c * N_ASSETS + i];
        W += d_pw[c * N_ASSETS + i];
    }
    float z = W / L + wf_b[0];
    out[i] = 1.0f / (1.0f + __expf(-z));
}

// ============================================================================
// launch
// ============================================================================
extern "C" void kernel_launch(void* const* d_in, const int* in_sizes, int n_in,
                              void* d_out, int out_size) {
    const float* S        = (const float*)d_in[0];
    const float* ranks    = (const float*)d_in[1];
    const float* Wq_w     = (const float*)d_in[2];
    const float* Wq_b     = (const float*)d_in[3];
    const float* Wk_w     = (const float*)d_in[4];
    const float* Wk_b     = (const float*)d_in[5];
    const float* Wv_w     = (const float*)d_in[6];
    const float* Wv_b     = (const float*)d_in[7];
    const float* rank_emb = (const float*)d_in[8];
    const float* wL_w     = (const float*)d_in[9];
    const float* wL_b     = (const float*)d_in[10];
    const float* wf_w     = (const float*)d_in[11];
    const float* wf_b     = (const float*)d_in[12];
    float* out = (float*)d_out;

    static int attr_set = 0;
    if (!attr_set) {
        cudaFuncSetAttribute(attn_kernel,
                             cudaFuncAttributeMaxDynamicSharedMemorySize, SMEM_TOTAL);
        cudaFuncSetAttribute(proj_mma_kernel,
                             cudaFuncAttributeMaxDynamicSharedMemorySize, PSM_TOTAL);
        attr_set = 1;
    }

    prep_kernel<<<85, 256>>>(rank_emb, wL_w, wL_b, Wv_w, wf_w, Wv_b, Wq_w, Wk_w);
    convS_kernel<<<128, 256>>>(S);
    proj_mma_kernel<<<dim3(64, 2), 256, PSM_TOTAL>>>(Wq_b, Wk_b);
    attn_kernel<<<dim3(32, NCHUNK), 512, SMEM_TOTAL>>>(ranks);
    combine_kernel<<<16, 256>>>(wf_b, out);
}